// round 8
// baseline (speedup 1.0000x reference)
#include <cuda_runtime.h>
#include <math.h>

#define N_NODES 50000
#define N_EDGES 800000

// ---- scratch (device globals; no allocation allowed) ----
__device__ __align__(16) float g_h1[N_NODES * 256];
__device__ __align__(16) float g_h2[N_NODES * 256];
__device__ __align__(16) float g_z [N_NODES * 256];
__device__ float g_sim[N_EDGES];          // CSR order, raw thresholded sims
__device__ float g_w  [N_EDGES];          // compacted exp-weights
__device__ int   g_ccol[N_EDGES];         // CSR order: col of slot j
__device__ int   g_ccol2[N_EDGES];        // compacted cols
__device__ int   g_crow[N_EDGES];         // CSR order: row of slot j
__device__ float g_rnrm[N_NODES];
__device__ float g_wself[N_NODES];
__device__ int   g_rowptr[N_NODES + 1];
__device__ int   g_rowend[N_NODES];       // end of compacted segment
__device__ int   g_wr[N_NODES];
__device__ int   g_cnt[N_NODES];

// ================= CSR build (row/col fixed across the 3 layers) =============
__global__ void k_zero_cnt() {
    int i = blockIdx.x * blockDim.x + threadIdx.x;
    if (i < N_NODES) g_cnt[i] = 0;
}

__global__ void k_hist(const int* __restrict__ row) {
    for (int e = blockIdx.x * blockDim.x + threadIdx.x; e < N_EDGES;
         e += gridDim.x * blockDim.x)
        atomicAdd(&g_cnt[row[e]], 1);
}

// single-block exclusive scan over 50000 counts
__global__ void k_scan() {
    __shared__ int wsum[32];
    __shared__ int carry;
    int tid = threadIdx.x, lane = tid & 31, wid = tid >> 5;
    if (tid == 0) carry = 0;
    __syncthreads();
    for (int base = 0; base < N_NODES; base += 1024) {
        int i = base + tid;
        int v = (i < N_NODES) ? g_cnt[i] : 0;
        int inc = v;
#pragma unroll
        for (int o = 1; o < 32; o <<= 1) {
            int y = __shfl_up_sync(0xffffffffu, inc, o);
            if (lane >= o) inc += y;
        }
        if (lane == 31) wsum[wid] = inc;
        __syncthreads();
        if (wid == 0) {
            int w = wsum[lane];
#pragma unroll
            for (int o = 1; o < 32; o <<= 1) {
                int y = __shfl_up_sync(0xffffffffu, w, o);
                if (lane >= o) w += y;
            }
            wsum[lane] = w;
        }
        __syncthreads();
        int pre = (wid > 0) ? wsum[wid - 1] : 0;
        int excl = carry + pre + inc - v;
        if (i < N_NODES) { g_rowptr[i] = excl; g_wr[i] = excl; }
        int chunk_total = wsum[31];
        __syncthreads();
        if (tid == 0) carry += chunk_total;
        __syncthreads();
    }
    if (tid == 0) g_rowptr[N_NODES] = carry;
}

__global__ void k_scatter(const int* __restrict__ row, const int* __restrict__ col) {
    for (int e = blockIdx.x * blockDim.x + threadIdx.x; e < N_EDGES;
         e += gridDim.x * blockDim.x) {
        int r = row[e];
        int p = atomicAdd(&g_wr[r], 1);
        g_ccol[p] = col[e];
        g_crow[p] = r;
    }
}

// ================= per-layer kernels =========================================
// reciprocal node norms (only needed for raw x; later layers fold into agg)
template <int IN>
__global__ void k_norms(const float* __restrict__ x) {
    int n = (blockIdx.x * blockDim.x + threadIdx.x) >> 5;
    if (n >= N_NODES) return;
    int lane = threadIdx.x & 31;
    const float4* xr = (const float4*)(x + (size_t)n * IN);
    float s = 0.0f;
#pragma unroll
    for (int i = 0; i < IN / 128; i++) {
        float4 v = xr[lane + 32 * i];
        s += v.x * v.x + v.y * v.y + v.z * v.z + v.w * v.w;
    }
#pragma unroll
    for (int o = 16; o; o >>= 1) s += __shfl_xor_sync(0xffffffffu, s, o);
    if (lane == 0) g_rnrm[n] = 1.0f / fmaxf(sqrtf(s), 1e-12f);
}

// ====== FUSED kernel: blocks [0,gemmBlocks) do GEMM, rest do SDDMM ==========
// OUTKIND 0: Z[n, f] = X·W per head, BN=128 (two heads of 64), OUTF=256
// OUTKIND 1: Z[n, o] = X·W2, OUTF=16
// SDDMM: warp handles U consecutive CSR slots, loads front-batched.
template <int IN, int U, int OUTKIND>
__global__ void __launch_bounds__(256) k_simgemm(const float* __restrict__ X,
                                                 const float* __restrict__ W,
                                                 float* __restrict__ Z,
                                                 int gemmBlocks, int mBlocks) {
    __shared__ float sA[16][132];
    __shared__ float sB[16][132];
    int tid = threadIdx.x;

    if (blockIdx.x < gemmBlocks) {
        if (OUTKIND == 0) {
            // ---- BM=128, BN=128 (heads hp*2, hp*2+1), BK=16, 8x8 per thread ----
            int mb = blockIdx.x % mBlocks;
            int hp = blockIdx.x / mBlocks;
            int n0 = mb * 128;
            int f0 = hp * 128;
            int tx = tid & 15, ty = tid >> 4;
            float acc[8][8];
#pragma unroll
            for (int i = 0; i < 8; i++)
#pragma unroll
                for (int j = 0; j < 8; j++) acc[i][j] = 0.0f;

            for (int k0 = 0; k0 < IN; k0 += 16) {
                // X tile: 128 rows x 16 d -> transposed. 512 float4 / 256 thr.
#pragma unroll
                for (int t = 0; t < 2; t++) {
                    int idx = tid + t * 256;
                    int r = idx >> 2, c4 = (idx & 3) * 4;
                    int n = n0 + r;
                    float4 v = (n < N_NODES)
                                   ? *(const float4*)&X[(size_t)n * IN + k0 + c4]
                                   : make_float4(0.f, 0.f, 0.f, 0.f);
                    sA[c4 + 0][r] = v.x;
                    sA[c4 + 1][r] = v.y;
                    sA[c4 + 2][r] = v.z;
                    sA[c4 + 3][r] = v.w;
                }
                // W tile: 16 x 128 (two heads). 512 float4 / 256 thr.
#pragma unroll
                for (int t = 0; t < 2; t++) {
                    int idx = tid + t * 256;
                    int kk = idx >> 5, f4 = (idx & 31) * 4;
                    int head = hp * 2 + (f4 >> 6);
                    int o = f4 & 63;
                    *(float4*)&sB[kk][f4] =
                        *(const float4*)&W[((size_t)head * IN + k0 + kk) * 64 + o];
                }
                __syncthreads();
#pragma unroll
                for (int k = 0; k < 16; k++) {
                    float av[8], bv[8];
                    *(float4*)(av + 0) = *(const float4*)&sA[k][ty * 8 + 0];
                    *(float4*)(av + 4) = *(const float4*)&sA[k][ty * 8 + 4];
                    *(float4*)(bv + 0) = *(const float4*)&sB[k][tx * 8 + 0];
                    *(float4*)(bv + 4) = *(const float4*)&sB[k][tx * 8 + 4];
#pragma unroll
                    for (int i = 0; i < 8; i++)
#pragma unroll
                        for (int j = 0; j < 8; j++) acc[i][j] += av[i] * bv[j];
                }
                __syncthreads();
            }
#pragma unroll
            for (int i = 0; i < 8; i++) {
                int n = n0 + ty * 8 + i;
                if (n < N_NODES) {
                    float4 v0 = make_float4(acc[i][0], acc[i][1], acc[i][2], acc[i][3]);
                    float4 v1 = make_float4(acc[i][4], acc[i][5], acc[i][6], acc[i][7]);
                    *(float4*)&Z[(size_t)n * 256 + f0 + tx * 8 + 0] = v0;
                    *(float4*)&Z[(size_t)n * 256 + f0 + tx * 8 + 4] = v1;
                }
            }
        } else {
            // ---- small GEMM: BM=64, OUT=16 ----
            int tx = tid % 16, ty = tid / 16;
            int n0 = blockIdx.x * 64;
            float acc[4] = {0.f, 0.f, 0.f, 0.f};
            for (int k0 = 0; k0 < IN; k0 += 16) {
                {
                    int r = tid >> 2, c4 = (tid & 3) * 4;
                    int n = n0 + r;
                    float4 v = (n < N_NODES)
                                   ? *(const float4*)&X[(size_t)n * IN + k0 + c4]
                                   : make_float4(0.f, 0.f, 0.f, 0.f);
                    sA[c4 + 0][r] = v.x;
                    sA[c4 + 1][r] = v.y;
                    sA[c4 + 2][r] = v.z;
                    sA[c4 + 3][r] = v.w;
                }
                if (tid < 64) {
                    int kk = tid >> 2, f4 = (tid & 3) * 4;
                    *(float4*)&sB[kk][f4] = *(const float4*)&W[(size_t)(k0 + kk) * 16 + f4];
                }
                __syncthreads();
#pragma unroll
                for (int k = 0; k < 16; k++) {
                    float w = sB[k][tx];
                    float4 a = *(const float4*)&sA[k][ty * 4];
                    acc[0] += a.x * w;
                    acc[1] += a.y * w;
                    acc[2] += a.z * w;
                    acc[3] += a.w * w;
                }
                __syncthreads();
            }
#pragma unroll
            for (int i = 0; i < 4; i++) {
                int n = n0 + ty * 4 + i;
                if (n < N_NODES) Z[(size_t)n * 16 + tx] = acc[i];
            }
        }
        return;
    }

    // -------------------- SDDMM part --------------------
    int w = ((blockIdx.x - gemmBlocks) * 256 + tid) >> 5;
    int j0 = w * U;
    if (j0 >= N_EDGES) return;
    int lane = tid & 31;
    constexpr int V = IN / 128;
    int rr[U], cc[U];
#pragma unroll
    for (int u = 0; u < U; u++) {
        int j = j0 + u;
        if (j > N_EDGES - 1) j = N_EDGES - 1;
        rr[u] = g_crow[j];
        cc[u] = g_ccol[j];
    }
    float4 a[U][V], b[U][V];
#pragma unroll
    for (int u = 0; u < U; u++) {
        const float4* xa = (const float4*)(X + (size_t)rr[u] * IN);
        const float4* xb = (const float4*)(X + (size_t)cc[u] * IN);
#pragma unroll
        for (int i = 0; i < V; i++) {
            a[u][i] = xa[lane + 32 * i];
            b[u][i] = xb[lane + 32 * i];
        }
    }
    float s[U];
#pragma unroll
    for (int u = 0; u < U; u++) {
        float t = 0.0f;
#pragma unroll
        for (int i = 0; i < V; i++)
            t += a[u][i].x * b[u][i].x + a[u][i].y * b[u][i].y +
                 a[u][i].z * b[u][i].z + a[u][i].w * b[u][i].w;
        s[u] = t;
    }
#pragma unroll
    for (int o = 16; o; o >>= 1)
#pragma unroll
        for (int u = 0; u < U; u++) s[u] += __shfl_xor_sync(0xffffffffu, s[u], o);
    if (lane == 0) {
#pragma unroll
        for (int u = 0; u < U; u++) {
            int j = j0 + u;
            if (j < N_EDGES) {
                float sim = s[u] * g_rnrm[rr[u]] * g_rnrm[cc[u]];
                g_sim[j] = (sim < 0.1f) ? 0.0f : sim;
            }
        }
    }
}

// rowsum + degree + nonzero compaction + exp-weight precompute (warp per node)
__global__ void k_rowdeg() {
    int n = (blockIdx.x * blockDim.x + threadIdx.x) >> 5;
    if (n >= N_NODES) return;
    int lane = threadIdx.x & 31;
    int b = g_rowptr[n], e2 = g_rowptr[n + 1];
    float s = 0.0f;
    int cnt = 0;
    int wpos = b;
    for (int base = b; base < e2; base += 32) {
        int j = base + lane;
        float v = (j < e2) ? g_sim[j] : 0.0f;
        int c = (j < e2) ? g_ccol[j] : 0;
        bool nz = (v != 0.0f);
        unsigned m = __ballot_sync(0xffffffffu, nz);
        int pos = __popc(m & ((1u << lane) - 1u));
        if (nz) {
            g_w[wpos + pos] = v;
            g_ccol2[wpos + pos] = c;
        }
        s += v;
        cnt += nz;
        wpos += __popc(m);
    }
#pragma unroll
    for (int o = 16; o; o >>= 1) {
        s += __shfl_xor_sync(0xffffffffu, s, o);
        cnt += __shfl_xor_sync(0xffffffffu, cnt, o);
    }
    float irs = (s > 0.0f) ? (1.0f / s) : 0.0f;
    for (int j = b + lane; j < wpos; j += 32) g_w[j] = __expf(g_w[j] * irs);
    if (lane == 0) {
        g_rowend[n] = wpos;
        g_wself[n] = __expf(1.0f / (float)(cnt + 1));
    }
}

// warp-per-node aggregation over compacted weights; optionally writes
// reciprocal norm of the OUTPUT row (used by next layer's SDDMM).
template <bool RELU, bool WRITENORM>
__global__ void k_agg(const float* __restrict__ z, float* __restrict__ out) {
    constexpr int OUTF = 256;
    int n = (blockIdx.x * blockDim.x + threadIdx.x) >> 5;
    if (n >= N_NODES) return;
    int lane = threadIdx.x & 31;
    float ws = g_wself[n];
    float4 acc[2];
    const float4* zn = (const float4*)(z + (size_t)n * OUTF);
#pragma unroll
    for (int i = 0; i < 2; i++) {
        float4 v = zn[lane + 32 * i];
        acc[i] = make_float4(ws * v.x, ws * v.y, ws * v.z, ws * v.w);
    }
    int b = g_rowptr[n], e2 = g_rowend[n];
    int j = b;
    for (; j + 2 <= e2; j += 2) {
        float w0 = g_w[j], w1 = g_w[j + 1];
        int c0 = g_ccol2[j], c1 = g_ccol2[j + 1];
        const float4* z0 = (const float4*)(z + (size_t)c0 * OUTF);
        const float4* z1 = (const float4*)(z + (size_t)c1 * OUTF);
#pragma unroll
        for (int i = 0; i < 2; i++) {
            float4 v0 = z0[lane + 32 * i];
            float4 v1 = z1[lane + 32 * i];
            acc[i].x += w0 * v0.x + w1 * v1.x;
            acc[i].y += w0 * v0.y + w1 * v1.y;
            acc[i].z += w0 * v0.z + w1 * v1.z;
            acc[i].w += w0 * v0.w + w1 * v1.w;
        }
    }
    if (j < e2) {
        float w0 = g_w[j];
        const float4* z0 = (const float4*)(z + (size_t)g_ccol2[j] * OUTF);
#pragma unroll
        for (int i = 0; i < 2; i++) {
            float4 v0 = z0[lane + 32 * i];
            acc[i].x += w0 * v0.x;
            acc[i].y += w0 * v0.y;
            acc[i].z += w0 * v0.z;
            acc[i].w += w0 * v0.w;
        }
    }
    float nrm = 0.0f;
#pragma unroll
    for (int i = 0; i < 2; i++) {
        float4 v = acc[i];
        if (RELU) {
            v.x = (v.x >= 0.f) ? v.x : 0.01f * v.x;
            v.y = (v.y >= 0.f) ? v.y : 0.01f * v.y;
            v.z = (v.z >= 0.f) ? v.z : 0.01f * v.z;
            v.w = (v.w >= 0.f) ? v.w : 0.01f * v.w;
        }
        if (WRITENORM)
            nrm += v.x * v.x + v.y * v.y + v.z * v.z + v.w * v.w;
        ((float4*)(out + (size_t)n * OUTF))[lane + 32 * i] = v;
    }
    if (WRITENORM) {
#pragma unroll
        for (int o = 16; o; o >>= 1) nrm += __shfl_xor_sync(0xffffffffu, nrm, o);
        if (lane == 0) g_rnrm[n] = 1.0f / fmaxf(sqrtf(nrm), 1e-12f);
    }
}

// 16-wide aggregation: two nodes per warp (half-warp each), compacted weights.
__global__ void k_agg16(const float* __restrict__ z, float* __restrict__ out) {
    int w = (blockIdx.x * blockDim.x + threadIdx.x) >> 5;
    int lane = threadIdx.x & 31;
    int n = w * 2 + (lane >> 4);
    if (n >= N_NODES) return;
    int l = lane & 15;
    float acc = g_wself[n] * z[(size_t)n * 16 + l];
    int b = g_rowptr[n], e2 = g_rowend[n];
    int j = b;
    for (; j + 2 <= e2; j += 2) {
        float w0 = g_w[j], w1 = g_w[j + 1];
        int c0 = g_ccol2[j], c1 = g_ccol2[j + 1];
        acc += w0 * z[(size_t)c0 * 16 + l] + w1 * z[(size_t)c1 * 16 + l];
    }
    if (j < e2) acc += g_w[j] * z[(size_t)g_ccol2[j] * 16 + l];
    out[(size_t)n * 16 + l] = acc;
}

// ================= driver ====================================================
extern "C" void kernel_launch(void* const* d_in, const int* in_sizes, int n_in,
                              void* d_out, int out_size) {
    const float* x  = (const float*)d_in[0];
    const float* W0 = (const float*)d_in[1];   // [4,128,64]
    const float* W1 = (const float*)d_in[2];   // [4,256,64]
    const float* W2 = (const float*)d_in[3];   // [1,256,16]
    const int*   row = (const int*)d_in[4];
    const int*   col = (const int*)d_in[5];
    float* out = (float*)d_out;

    float *h1, *h2, *z;
    cudaGetSymbolAddress((void**)&h1, g_h1);
    cudaGetSymbolAddress((void**)&h2, g_h2);
    cudaGetSymbolAddress((void**)&z,  g_z);

    const int NODE_WARP_BLOCKS = (N_NODES * 32 + 255) / 256;   // 6250
    const int MB = (N_NODES + 127) / 128;                      // 391
    const int GEMM256 = MB * 2;                                // 782 (two head-pairs)
    const int GEMM16 = (N_NODES + 63) / 64;                    // 782
    const int SIM4 = (N_EDGES + 31) / 32;                      // 25000 blocks (U=4)
    const int SIM2 = (N_EDGES + 15) / 16;                      // 50000 blocks (U=2)

    // ---- CSR (shared by all three layers) ----
    k_zero_cnt<<<(N_NODES + 255) / 256, 256>>>();
    k_hist<<<400, 256>>>(row);
    k_scan<<<1, 1024>>>();
    k_scatter<<<400, 256>>>(row, col);

    // ---- layer 0: sim0 || gemm0(x->z), then agg(+relu,+norm) -> h1 ----
    k_norms<128><<<NODE_WARP_BLOCKS, 256>>>(x);
    k_simgemm<128, 4, 0><<<GEMM256 + SIM4, 256>>>(x, W0, z, GEMM256, MB);
    k_rowdeg<<<NODE_WARP_BLOCKS, 256>>>();
    k_agg<true, true><<<NODE_WARP_BLOCKS, 256>>>(z, h1);

    // ---- layer 1: sim1 || gemm1(h1->z), then agg(+relu,+norm) -> h2 ----
    k_simgemm<256, 2, 0><<<GEMM256 + SIM2, 256>>>(h1, W1, z, GEMM256, MB);
    k_rowdeg<<<NODE_WARP_BLOCKS, 256>>>();
    k_agg<true, true><<<NODE_WARP_BLOCKS, 256>>>(z, h2);

    // ---- layer 2: sim2 || gemm2(h2->z16), then agg16 -> out ----
    k_simgemm<256, 2, 1><<<GEMM16 + SIM2, 256>>>(h2, W2, z, GEMM16, 0);
    k_rowdeg<<<NODE_WARP_BLOCKS, 256>>>();
    k_agg16<<<(N_NODES / 2 * 32 + 255) / 256, 256>>>(z, out);
}

// round 9
// speedup vs baseline: 1.2983x; 1.2983x over previous
#include <cuda_runtime.h>
#include <math.h>

#define N_NODES 50000
#define N_EDGES 800000

// ---- scratch (device globals; no allocation allowed) ----
__device__ __align__(16) float g_h1[N_NODES * 256];
__device__ __align__(16) float g_h2[N_NODES * 256];
__device__ __align__(16) float g_z [N_NODES * 256];
__device__ float g_sim[N_EDGES];          // CSR order, raw thresholded sims
__device__ float g_w  [N_EDGES];          // compacted exp-weights
__device__ int   g_ccol[N_EDGES];         // CSR order: col of slot j
__device__ int   g_ccol2[N_EDGES];        // compacted cols
__device__ int   g_crow[N_EDGES];         // CSR order: row of slot j
__device__ float g_rnrm[N_NODES];
__device__ float g_wself[N_NODES];
__device__ int   g_rowptr[N_NODES + 1];
__device__ int   g_rowend[N_NODES];       // end of compacted segment
__device__ int   g_wr[N_NODES];
__device__ int   g_cnt[N_NODES];

// ================= CSR build (row/col fixed across the 3 layers) =============
__global__ void k_zero_cnt() {
    int i = blockIdx.x * blockDim.x + threadIdx.x;
    if (i < N_NODES) g_cnt[i] = 0;
}

__global__ void k_hist(const int* __restrict__ row) {
    for (int e = blockIdx.x * blockDim.x + threadIdx.x; e < N_EDGES;
         e += gridDim.x * blockDim.x)
        atomicAdd(&g_cnt[row[e]], 1);
}

// single-block exclusive scan over 50000 counts
__global__ void k_scan() {
    __shared__ int wsum[32];
    __shared__ int carry;
    int tid = threadIdx.x, lane = tid & 31, wid = tid >> 5;
    if (tid == 0) carry = 0;
    __syncthreads();
    for (int base = 0; base < N_NODES; base += 1024) {
        int i = base + tid;
        int v = (i < N_NODES) ? g_cnt[i] : 0;
        int inc = v;
#pragma unroll
        for (int o = 1; o < 32; o <<= 1) {
            int y = __shfl_up_sync(0xffffffffu, inc, o);
            if (lane >= o) inc += y;
        }
        if (lane == 31) wsum[wid] = inc;
        __syncthreads();
        if (wid == 0) {
            int w = wsum[lane];
#pragma unroll
            for (int o = 1; o < 32; o <<= 1) {
                int y = __shfl_up_sync(0xffffffffu, w, o);
                if (lane >= o) w += y;
            }
            wsum[lane] = w;
        }
        __syncthreads();
        int pre = (wid > 0) ? wsum[wid - 1] : 0;
        int excl = carry + pre + inc - v;
        if (i < N_NODES) { g_rowptr[i] = excl; g_wr[i] = excl; }
        int chunk_total = wsum[31];
        __syncthreads();
        if (tid == 0) carry += chunk_total;
        __syncthreads();
    }
    if (tid == 0) g_rowptr[N_NODES] = carry;
}

__global__ void k_scatter(const int* __restrict__ row, const int* __restrict__ col) {
    for (int e = blockIdx.x * blockDim.x + threadIdx.x; e < N_EDGES;
         e += gridDim.x * blockDim.x) {
        int r = row[e];
        int p = atomicAdd(&g_wr[r], 1);
        g_ccol[p] = col[e];
        g_crow[p] = r;
    }
}

// ================= per-layer kernels =========================================
// reciprocal node norms (raw x only; later layers fold into agg)
template <int IN>
__global__ void k_norms(const float* __restrict__ x) {
    int n = (blockIdx.x * blockDim.x + threadIdx.x) >> 5;
    if (n >= N_NODES) return;
    int lane = threadIdx.x & 31;
    const float4* xr = (const float4*)(x + (size_t)n * IN);
    float s = 0.0f;
#pragma unroll
    for (int i = 0; i < IN / 128; i++) {
        float4 v = xr[lane + 32 * i];
        s += v.x * v.x + v.y * v.y + v.z * v.z + v.w * v.w;
    }
#pragma unroll
    for (int o = 16; o; o >>= 1) s += __shfl_xor_sync(0xffffffffu, s, o);
    if (lane == 0) g_rnrm[n] = 1.0f / fmaxf(sqrtf(s), 1e-12f);
}

// warp-per-U-CSR-slots SDDMM, loads front-batched for MLP.
template <int IN, int U>
__global__ void k_sim(const float* __restrict__ x) {
    int w = (blockIdx.x * blockDim.x + threadIdx.x) >> 5;
    int j0 = w * U;
    if (j0 >= N_EDGES) return;
    int lane = threadIdx.x & 31;
    constexpr int V = IN / 128;
    int rr[U], cc[U];
#pragma unroll
    for (int u = 0; u < U; u++) {
        int j = j0 + u;
        if (j > N_EDGES - 1) j = N_EDGES - 1;
        rr[u] = g_crow[j];
        cc[u] = g_ccol[j];
    }
    float4 a[U][V], b[U][V];
#pragma unroll
    for (int u = 0; u < U; u++) {
        const float4* xa = (const float4*)(x + (size_t)rr[u] * IN);
        const float4* xb = (const float4*)(x + (size_t)cc[u] * IN);
#pragma unroll
        for (int i = 0; i < V; i++) {
            a[u][i] = xa[lane + 32 * i];
            b[u][i] = xb[lane + 32 * i];
        }
    }
    float s[U];
#pragma unroll
    for (int u = 0; u < U; u++) {
        float t = 0.0f;
#pragma unroll
        for (int i = 0; i < V; i++)
            t += a[u][i].x * b[u][i].x + a[u][i].y * b[u][i].y +
                 a[u][i].z * b[u][i].z + a[u][i].w * b[u][i].w;
        s[u] = t;
    }
#pragma unroll
    for (int o = 16; o; o >>= 1)
#pragma unroll
        for (int u = 0; u < U; u++) s[u] += __shfl_xor_sync(0xffffffffu, s[u], o);
    if (lane == 0) {
#pragma unroll
        for (int u = 0; u < U; u++) {
            int j = j0 + u;
            if (j < N_EDGES) {
                float sim = s[u] * g_rnrm[rr[u]] * g_rnrm[cc[u]];
                g_sim[j] = (sim < 0.1f) ? 0.0f : sim;
            }
        }
    }
}

// rowsum + degree + nonzero compaction + exp-weight precompute (warp per node)
__global__ void k_rowdeg() {
    int n = (blockIdx.x * blockDim.x + threadIdx.x) >> 5;
    if (n >= N_NODES) return;
    int lane = threadIdx.x & 31;
    int b = g_rowptr[n], e2 = g_rowptr[n + 1];
    float s = 0.0f;
    int cnt = 0;
    int wpos = b;
    for (int base = b; base < e2; base += 32) {
        int j = base + lane;
        float v = (j < e2) ? g_sim[j] : 0.0f;
        int c = (j < e2) ? g_ccol[j] : 0;
        bool nz = (v != 0.0f);
        unsigned m = __ballot_sync(0xffffffffu, nz);
        int pos = __popc(m & ((1u << lane) - 1u));
        if (nz) {
            g_w[wpos + pos] = v;
            g_ccol2[wpos + pos] = c;
        }
        s += v;
        cnt += nz;
        wpos += __popc(m);
    }
#pragma unroll
    for (int o = 16; o; o >>= 1) {
        s += __shfl_xor_sync(0xffffffffu, s, o);
        cnt += __shfl_xor_sync(0xffffffffu, cnt, o);
    }
    float irs = (s > 0.0f) ? (1.0f / s) : 0.0f;
    for (int j = b + lane; j < wpos; j += 32) g_w[j] = __expf(g_w[j] * irs);
    if (lane == 0) {
        g_rowend[n] = wpos;
        g_wself[n] = __expf(1.0f / (float)(cnt + 1));
    }
}

// ====== 8x8 register-tiled SGEMM (R7-proven), one head per blockIdx.y ======
template <int IN>
__global__ void __launch_bounds__(128) k_gemm8(const float* __restrict__ X,
                                               const float* __restrict__ W,
                                               float* __restrict__ Z,
                                               int OUTF) {
    constexpr int BM = 128, BN = 64, BK = 16;
    __shared__ float sXT[BK][BM + 4];
    __shared__ float sW[BK][BN + 4];
    int tid = threadIdx.x;
    int n0 = blockIdx.x * BM;
    int h = blockIdx.y;
    int f0 = h * BN;
    int tx = tid & 7, ty = tid >> 3;
    float acc[8][8];
#pragma unroll
    for (int i = 0; i < 8; i++)
#pragma unroll
        for (int jj = 0; jj < 8; jj++) acc[i][jj] = 0.0f;

    for (int k0 = 0; k0 < IN; k0 += BK) {
        {
            int n = n0 + tid;
#pragma unroll
            for (int i = 0; i < 4; i++) {
                float4 v = (n < N_NODES)
                               ? *(const float4*)&X[(size_t)n * IN + k0 + i * 4]
                               : make_float4(0.f, 0.f, 0.f, 0.f);
                sXT[i * 4 + 0][tid] = v.x;
                sXT[i * 4 + 1][tid] = v.y;
                sXT[i * 4 + 2][tid] = v.z;
                sXT[i * 4 + 3][tid] = v.w;
            }
        }
        {
#pragma unroll
            for (int t = 0; t < 2; t++) {
                int idx = tid + t * 128;
                int kk = idx >> 4, f4 = (idx & 15) * 4;
                *(float4*)&sW[kk][f4] =
                    *(const float4*)&W[((size_t)h * IN + k0 + kk) * 64 + f4];
            }
        }
        __syncthreads();
#pragma unroll
        for (int k = 0; k < BK; k++) {
            float av[8], bv[8];
            *(float4*)(av + 0) = *(const float4*)&sXT[k][ty * 8 + 0];
            *(float4*)(av + 4) = *(const float4*)&sXT[k][ty * 8 + 4];
            *(float4*)(bv + 0) = *(const float4*)&sW[k][tx * 8 + 0];
            *(float4*)(bv + 4) = *(const float4*)&sW[k][tx * 8 + 4];
#pragma unroll
            for (int i = 0; i < 8; i++)
#pragma unroll
                for (int jj = 0; jj < 8; jj++) acc[i][jj] += av[i] * bv[jj];
        }
        __syncthreads();
    }
#pragma unroll
    for (int i = 0; i < 8; i++) {
        int n = n0 + ty * 8 + i;
        if (n < N_NODES) {
            float4 v0 = make_float4(acc[i][0], acc[i][1], acc[i][2], acc[i][3]);
            float4 v1 = make_float4(acc[i][4], acc[i][5], acc[i][6], acc[i][7]);
            *(float4*)&Z[(size_t)n * OUTF + f0 + tx * 8 + 0] = v0;
            *(float4*)&Z[(size_t)n * OUTF + f0 + tx * 8 + 4] = v1;
        }
    }
}

// small GEMM for layer 2: Z[n, o] = sum_d X[n,d] * W2[d,o], OUTF=16
__global__ void __launch_bounds__(256) k_gemm16(const float* __restrict__ X,
                                                const float* __restrict__ W,
                                                float* __restrict__ Z) {
    constexpr int IN = 256, BM = 64, BK = 16;
    __shared__ float sXT[BK][BM + 4];
    __shared__ float sW[BK][16 + 4];
    int tid = threadIdx.x;
    int tx = tid % 16, ty = tid / 16;
    int n0 = blockIdx.x * BM;
    float acc[4] = {0.f, 0.f, 0.f, 0.f};
    for (int k0 = 0; k0 < IN; k0 += BK) {
        {
            int r = tid >> 2, c4 = (tid & 3) * 4;
            int n = n0 + r;
            float4 v = (n < N_NODES)
                           ? *(const float4*)&X[(size_t)n * IN + k0 + c4]
                           : make_float4(0.f, 0.f, 0.f, 0.f);
            sXT[c4 + 0][r] = v.x;
            sXT[c4 + 1][r] = v.y;
            sXT[c4 + 2][r] = v.z;
            sXT[c4 + 3][r] = v.w;
        }
        if (tid < 64) {
            int kk = tid >> 2, f4 = (tid & 3) * 4;
            *(float4*)&sW[kk][f4] = *(const float4*)&W[(size_t)(k0 + kk) * 16 + f4];
        }
        __syncthreads();
#pragma unroll
        for (int k = 0; k < BK; k++) {
            float w = sW[k][tx];
            float4 a = *(const float4*)&sXT[k][ty * 4];
            acc[0] += a.x * w;
            acc[1] += a.y * w;
            acc[2] += a.z * w;
            acc[3] += a.w * w;
        }
        __syncthreads();
    }
#pragma unroll
    for (int i = 0; i < 4; i++) {
        int n = n0 + ty * 4 + i;
        if (n < N_NODES) Z[(size_t)n * 16 + tx] = acc[i];
    }
}

// warp-per-node aggregation over compacted weights (256-wide), float4 gathers,
// 2-unrolled; optionally fused leaky-relu and output-row reciprocal norm.
template <bool RELU, bool WRITENORM>
__global__ void k_agg(const float* __restrict__ z, float* __restrict__ out) {
    constexpr int OUTF = 256;
    int n = (blockIdx.x * blockDim.x + threadIdx.x) >> 5;
    if (n >= N_NODES) return;
    int lane = threadIdx.x & 31;
    float ws = g_wself[n];
    float4 acc[2];
    const float4* zn = (const float4*)(z + (size_t)n * OUTF);
#pragma unroll
    for (int i = 0; i < 2; i++) {
        float4 v = zn[lane + 32 * i];
        acc[i] = make_float4(ws * v.x, ws * v.y, ws * v.z, ws * v.w);
    }
    int b = g_rowptr[n], e2 = g_rowend[n];
    int j = b;
    for (; j + 2 <= e2; j += 2) {
        float w0 = g_w[j], w1 = g_w[j + 1];
        int c0 = g_ccol2[j], c1 = g_ccol2[j + 1];
        const float4* z0 = (const float4*)(z + (size_t)c0 * OUTF);
        const float4* z1 = (const float4*)(z + (size_t)c1 * OUTF);
#pragma unroll
        for (int i = 0; i < 2; i++) {
            float4 v0 = z0[lane + 32 * i];
            float4 v1 = z1[lane + 32 * i];
            acc[i].x += w0 * v0.x + w1 * v1.x;
            acc[i].y += w0 * v0.y + w1 * v1.y;
            acc[i].z += w0 * v0.z + w1 * v1.z;
            acc[i].w += w0 * v0.w + w1 * v1.w;
        }
    }
    if (j < e2) {
        float w0 = g_w[j];
        const float4* z0 = (const float4*)(z + (size_t)g_ccol2[j] * OUTF);
#pragma unroll
        for (int i = 0; i < 2; i++) {
            float4 v0 = z0[lane + 32 * i];
            acc[i].x += w0 * v0.x;
            acc[i].y += w0 * v0.y;
            acc[i].z += w0 * v0.z;
            acc[i].w += w0 * v0.w;
        }
    }
    float nrm = 0.0f;
#pragma unroll
    for (int i = 0; i < 2; i++) {
        float4 v = acc[i];
        if (RELU) {
            v.x = (v.x >= 0.f) ? v.x : 0.01f * v.x;
            v.y = (v.y >= 0.f) ? v.y : 0.01f * v.y;
            v.z = (v.z >= 0.f) ? v.z : 0.01f * v.z;
            v.w = (v.w >= 0.f) ? v.w : 0.01f * v.w;
        }
        if (WRITENORM)
            nrm += v.x * v.x + v.y * v.y + v.z * v.z + v.w * v.w;
        ((float4*)(out + (size_t)n * OUTF))[lane + 32 * i] = v;
    }
    if (WRITENORM) {
#pragma unroll
        for (int o = 16; o; o >>= 1) nrm += __shfl_xor_sync(0xffffffffu, nrm, o);
        if (lane == 0) g_rnrm[n] = 1.0f / fmaxf(sqrtf(nrm), 1e-12f);
    }
}

// 16-wide aggregation: two nodes per warp (half-warp each), compacted weights.
__global__ void k_agg16(const float* __restrict__ z, float* __restrict__ out) {
    int w = (blockIdx.x * blockDim.x + threadIdx.x) >> 5;
    int lane = threadIdx.x & 31;
    int n = w * 2 + (lane >> 4);
    if (n >= N_NODES) return;
    int l = lane & 15;
    float acc = g_wself[n] * z[(size_t)n * 16 + l];
    int b = g_rowptr[n], e2 = g_rowend[n];
    int j = b;
    for (; j + 2 <= e2; j += 2) {
        float w0 = g_w[j], w1 = g_w[j + 1];
        int c0 = g_ccol2[j], c1 = g_ccol2[j + 1];
        acc += w0 * z[(size_t)c0 * 16 + l] + w1 * z[(size_t)c1 * 16 + l];
    }
    if (j < e2) acc += g_w[j] * z[(size_t)g_ccol2[j] * 16 + l];
    out[(size_t)n * 16 + l] = acc;
}

// ================= driver ====================================================
extern "C" void kernel_launch(void* const* d_in, const int* in_sizes, int n_in,
                              void* d_out, int out_size) {
    const float* x  = (const float*)d_in[0];
    const float* W0 = (const float*)d_in[1];   // [4,128,64]
    const float* W1 = (const float*)d_in[2];   // [4,256,64]
    const float* W2 = (const float*)d_in[3];   // [1,256,16]
    const int*   row = (const int*)d_in[4];
    const int*   col = (const int*)d_in[5];
    float* out = (float*)d_out;

    float *h1, *h2, *z;
    cudaGetSymbolAddress((void**)&h1, g_h1);
    cudaGetSymbolAddress((void**)&h2, g_h2);
    cudaGetSymbolAddress((void**)&z,  g_z);

    // side stream + events, created once (host objects only; no device memory)
    static cudaStream_t s1 = nullptr;
    static cudaEvent_t ev[6];
    if (s1 == nullptr) {
        cudaStreamCreateWithFlags(&s1, cudaStreamNonBlocking);
        for (int i = 0; i < 6; i++)
            cudaEventCreateWithFlags(&ev[i], cudaEventDisableTiming);
    }

    const int NODE_WARP_BLOCKS = (N_NODES * 32 + 255) / 256;        // 6250
    const int SIM4_BLOCKS = ((N_EDGES + 3) / 4 * 32 + 255) / 256;   // 25000
    const int SIM2_BLOCKS = ((N_EDGES + 1) / 2 * 32 + 255) / 256;   // 50000
    const int GEMM_MB = (N_NODES + 127) / 128;                      // 391

    // ---- fork: gemm0 (only needs x, W0) runs on s1 under the whole CSR+sim0 --
    cudaEventRecord(ev[0], 0);
    cudaStreamWaitEvent(s1, ev[0], 0);
    k_gemm8<128><<<dim3(GEMM_MB, 4), 128, 0, s1>>>(x, W0, z, 256);

    // ---- s0: CSR build + norms + sim0 + rowdeg0 ----
    k_zero_cnt<<<(N_NODES + 255) / 256, 256>>>();
    k_hist<<<400, 256>>>(row);
    k_scan<<<1, 1024>>>();
    k_scatter<<<400, 256>>>(row, col);
    k_norms<128><<<NODE_WARP_BLOCKS, 256>>>(x);
    k_sim<128, 4><<<SIM4_BLOCKS, 256>>>(x);
    k_rowdeg<<<NODE_WARP_BLOCKS, 256>>>();

    // ---- join, agg0 -> h1 (relu + write next-layer norms) ----
    cudaEventRecord(ev[1], s1);
    cudaStreamWaitEvent(0, ev[1], 0);
    k_agg<true, true><<<NODE_WARP_BLOCKS, 256>>>(z, h1);

    // ---- layer 1: gemm1 on s1  ||  sim1+rowdeg1 on s0 ----
    cudaEventRecord(ev[2], 0);
    cudaStreamWaitEvent(s1, ev[2], 0);
    k_gemm8<256><<<dim3(GEMM_MB, 4), 128, 0, s1>>>(h1, W1, z, 256);
    k_sim<256, 2><<<SIM2_BLOCKS, 256>>>(h1);
    k_rowdeg<<<NODE_WARP_BLOCKS, 256>>>();
    cudaEventRecord(ev[3], s1);
    cudaStreamWaitEvent(0, ev[3], 0);
    k_agg<true, true><<<NODE_WARP_BLOCKS, 256>>>(z, h2);

    // ---- layer 2: gemm2 on s1  ||  sim2+rowdeg2 on s0 ----
    cudaEventRecord(ev[4], 0);
    cudaStreamWaitEvent(s1, ev[4], 0);
    k_gemm16<<<(N_NODES + 63) / 64, 256, 0, s1>>>(h2, W2, z);
    k_sim<256, 2><<<SIM2_BLOCKS, 256>>>(h2);
    k_rowdeg<<<NODE_WARP_BLOCKS, 256>>>();
    cudaEventRecord(ev[5], s1);
    cudaStreamWaitEvent(0, ev[5], 0);
    k_agg16<<<(N_NODES / 2 * 32 + 255) / 256, 256>>>(z, out);
}